// round 17
// baseline (speedup 1.0000x reference)
#include <cuda_runtime.h>
#include <cuda_fp16.h>
#include <cstdint>

#define N_NODES 100000
#define N_EDGES 3200000
#define IN_FEAT 512
#define HID 32
#define SCAN_BLK 512
#define SCAN_NBLK ((N_NODES + SCAN_BLK - 1) / SCAN_BLK)   // 196

// ---------------- device scratch (static, no allocation) ----------------
__device__ int    g_degi[N_NODES];
__device__ float  g_dinv[N_NODES];
__device__ int    g_rowstart[N_NODES + 1];
__device__ int    g_cursor[N_NODES];
__device__ int    g_blocksum[SCAN_NBLK];
__device__ int    g_blockoff[SCAN_NBLK];
__device__ int    g_csrc[N_EDGES];
// h stored as fp16: row = 32 halfs = 64 B
__device__ __half g_h[(size_t)N_NODES * HID];    // ping
__device__ __half g_agg[(size_t)N_NODES * HID];  // pong

// ---------------- degree / CSR build ----------------
__global__ void zero_degi_kernel() {
    int i = blockIdx.x * blockDim.x + threadIdx.x;
    if (i < N_NODES) g_degi[i] = 0;
}

__global__ void degi_kernel(const int* __restrict__ dst) {
    int e = blockIdx.x * blockDim.x + threadIdx.x;
    if (e < N_EDGES) atomicAdd(&g_degi[dst[e]], 1);
}

// block-local exclusive scan of degrees; also computes dinv (fused).
__global__ void scan_block_kernel() {
    __shared__ int sh[SCAN_BLK];
    int i = blockIdx.x * SCAN_BLK + threadIdx.x;
    int v = (i < N_NODES) ? g_degi[i] : 0;
    if (i < N_NODES) g_dinv[i] = rsqrtf((float)v + 1.0f);
    sh[threadIdx.x] = v;
    __syncthreads();
    #pragma unroll
    for (int off = 1; off < SCAN_BLK; off <<= 1) {
        int t = (threadIdx.x >= off) ? sh[threadIdx.x - off] : 0;
        __syncthreads();
        sh[threadIdx.x] += t;
        __syncthreads();
    }
    if (i < N_NODES) g_rowstart[i] = sh[threadIdx.x] - v;
    if (threadIdx.x == SCAN_BLK - 1) g_blocksum[blockIdx.x] = sh[SCAN_BLK - 1];
}

// parallel scan of the 196 block sums (single 256-thread block).
__global__ void scan_tops_kernel() {
    __shared__ int sh[256];
    int t = threadIdx.x;
    int v = (t < SCAN_NBLK) ? g_blocksum[t] : 0;
    sh[t] = v;
    __syncthreads();
    #pragma unroll
    for (int off = 1; off < 256; off <<= 1) {
        int x = (t >= off) ? sh[t - off] : 0;
        __syncthreads();
        sh[t] += x;
        __syncthreads();
    }
    if (t < SCAN_NBLK) g_blockoff[t] = sh[t] - v;
    if (t == 255) g_rowstart[N_NODES] = sh[255];
}

__global__ void scan_add_kernel() {
    int i = blockIdx.x * blockDim.x + threadIdx.x;
    if (i < N_NODES) {
        int v = g_rowstart[i] + g_blockoff[i >> 9];
        g_rowstart[i] = v;
        g_cursor[i] = v;
    }
}

__global__ void fill_kernel(const int* __restrict__ src, const int* __restrict__ dst) {
    int e = blockIdx.x * blockDim.x + threadIdx.x;
    if (e < N_EDGES) {
        int d = dst[e];
        int pos = atomicAdd(&g_cursor[d], 1);
        g_csrc[pos] = src[e];
    }
}

// ---------------- GEMM1: TF32 mma, 3-stage cp.async pipeline ---------------
// [N,512] @ [512,32]. 256 threads, tile 128 rows x 32 cols, K-chunk 32,
// 3 smem stages, 2 chunks in flight via cp.async (X copied as raw fp32 bits,
// used directly as tf32 operands = truncation; W cvt.rna through registers).
// Smem pitch 36 words keeps frag loads conflict-free. Epilogue computes
// dinv = rsqrtf(deg+1) from g_degi (so gemm1 depends only on degi).
#define G1_ROWS 128
#define G1_TK 32
#define G1_NT (IN_FEAT / G1_TK)   // 16 chunks
#define G1_PITCH 36
#define G1_XWORDS (3 * G1_ROWS * G1_PITCH)          // 13824
#define G1_WWORDS (3 * HID * G1_PITCH)              // 3456
#define G1_SMEM_BYTES ((G1_XWORDS + G1_WWORDS) * 4) // 69120

__device__ __forceinline__ uint32_t f2tf32(float f) {
    uint32_t r;
    asm("cvt.rna.tf32.f32 %0, %1;" : "=r"(r) : "f"(f));
    return r;
}

__device__ __forceinline__ void cp_async16(uint32_t dst_smem, const void* src) {
    asm volatile("cp.async.cg.shared.global [%0], [%1], 16;"
                 :: "r"(dst_smem), "l"(src));
}
#define CP_COMMIT() asm volatile("cp.async.commit_group;" ::: "memory")
#define CP_WAIT(n)  asm volatile("cp.async.wait_group %0;" :: "n"(n) : "memory")

__device__ __forceinline__ void mma_tf32(float* d,
    uint32_t a0, uint32_t a1, uint32_t a2, uint32_t a3,
    uint32_t b0, uint32_t b1)
{
    asm volatile(
        "mma.sync.aligned.m16n8k8.row.col.f32.tf32.tf32.f32 "
        "{%0,%1,%2,%3}, {%4,%5,%6,%7}, {%8,%9}, {%0,%1,%2,%3};"
        : "+f"(d[0]), "+f"(d[1]), "+f"(d[2]), "+f"(d[3])
        : "r"(a0), "r"(a1), "r"(a2), "r"(a3), "r"(b0), "r"(b1));
}

__global__ __launch_bounds__(256) void gemm1_kernel(
    const float* __restrict__ x, const float* __restrict__ W,
    __half* __restrict__ hh)
{
    extern __shared__ uint32_t smem_dyn[];
    uint32_t* Xs  = smem_dyn;                 // [3][128][36]
    uint32_t* WsT = smem_dyn + G1_XWORDS;     // [3][32][36]  ([stage][col][k])

    int tid  = threadIdx.x;
    int warp = tid >> 5;
    int lane = tid & 31;
    int gid  = lane >> 2;
    int tig  = lane & 3;
    int rowbase = blockIdx.x * G1_ROWS;

    float acc[4][4];
    #pragma unroll
    for (int n = 0; n < 4; n++)
        #pragma unroll
        for (int q = 0; q < 4; q++) acc[n][q] = 0.f;

    // per-thread fixed load coords
    int xr[4], xc4[4];
    const float* xsrc[4];
    #pragma unroll
    for (int i = 0; i < 4; i++) {
        int flat = tid + i * 256;              // 0..1023
        xr[i]  = flat >> 3;                    // 0..127
        xc4[i] = flat & 7;                     // 0..7
        int gr = rowbase + xr[i];
        if (gr >= N_NODES) gr = N_NODES - 1;
        xsrc[i] = x + (size_t)gr * IN_FEAT + xc4[i] * 4;
    }
    int wk = tid >> 3;                         // 0..31
    int wc = tid & 7;                          // 0..7

    uint32_t smem_base = (uint32_t)__cvta_generic_to_shared(Xs);

    auto issueX = [&](int t) {
        int s = t % 3;
        int k0 = t * G1_TK;
        #pragma unroll
        for (int i = 0; i < 4; i++) {
            uint32_t dst = smem_base +
                ((s * G1_ROWS + xr[i]) * G1_PITCH + xc4[i] * 4) * 4;
            cp_async16(dst, xsrc[i] + k0);
        }
    };
    auto loadstsW = [&](int t) {
        int s = t % 3;
        int k0 = t * G1_TK;
        float4 wv = *(const float4*)(W + (size_t)(k0 + wk) * HID + wc * 4);
        uint32_t* wb = WsT + (size_t)s * HID * G1_PITCH;
        wb[(wc * 4 + 0) * G1_PITCH + wk] = f2tf32(wv.x);
        wb[(wc * 4 + 1) * G1_PITCH + wk] = f2tf32(wv.y);
        wb[(wc * 4 + 2) * G1_PITCH + wk] = f2tf32(wv.z);
        wb[(wc * 4 + 3) * G1_PITCH + wk] = f2tf32(wv.w);
    };

    // prologue: chunks 0 and 1 in flight
    issueX(0); CP_COMMIT();
    issueX(1); CP_COMMIT();
    loadstsW(0);
    loadstsW(1);
    CP_WAIT(1);
    __syncthreads();

    for (int t = 0; t < G1_NT; t++) {
        // issue chunk t+2 into the buffer freed by compute(t-1)
        if (t + 2 < G1_NT) {
            issueX(t + 2); CP_COMMIT();
            loadstsW(t + 2);
        }

        // compute chunk t
        {
            int s = t % 3;
            const uint32_t* xb = Xs + (size_t)s * G1_ROWS * G1_PITCH;
            const uint32_t* wb = WsT + (size_t)s * HID * G1_PITCH;
            int r0 = warp * 16 + gid;
            #pragma unroll
            for (int ks = 0; ks < 4; ks++) {
                uint32_t a0 = xb[(r0    ) * G1_PITCH + ks * 8 + tig    ];
                uint32_t a1 = xb[(r0 + 8) * G1_PITCH + ks * 8 + tig    ];
                uint32_t a2 = xb[(r0    ) * G1_PITCH + ks * 8 + tig + 4];
                uint32_t a3 = xb[(r0 + 8) * G1_PITCH + ks * 8 + tig + 4];
                #pragma unroll
                for (int n = 0; n < 4; n++) {
                    uint32_t b0 = wb[(n * 8 + gid) * G1_PITCH + ks * 8 + tig    ];
                    uint32_t b1 = wb[(n * 8 + gid) * G1_PITCH + ks * 8 + tig + 4];
                    mma_tf32(acc[n], a0, a1, a2, a3, b0, b1);
                }
            }
        }

        if (t + 1 < G1_NT) {
            if (t + 2 < G1_NT) { CP_WAIT(1); } else { CP_WAIT(0); }
        }
        __syncthreads();
    }

    // epilogue: dinv from g_degi; D-frag rows gid / gid+8, cols 2tig,2tig+1
    int row0 = rowbase + warp * 16 + gid;
    int row1 = row0 + 8;
    float d0 = rsqrtf((float)g_degi[(row0 < N_NODES) ? row0 : 0] + 1.0f);
    float d1 = rsqrtf((float)g_degi[(row1 < N_NODES) ? row1 : 0] + 1.0f);
    #pragma unroll
    for (int n = 0; n < 4; n++) {
        int col = n * 8 + tig * 2;
        if (row0 < N_NODES)
            *(__half2*)(&hh[(size_t)row0 * HID + col]) =
                __floats2half2_rn(acc[n][0] * d0, acc[n][1] * d0);
        if (row1 < N_NODES)
            *(__half2*)(&hh[(size_t)row1 * HID + col]) =
                __floats2half2_rn(acc[n][2] * d1, acc[n][3] * d1);
    }
}

// ---------------- fused gather + next-layer GEMM (fp16 h, R14 shape) -------
// warp per node, lane = feature column; one 64B coalesced __half load per
// edge across the warp; unconditional unrolled 32-edge blocks, dual acc chains.
// FROZEN: two restructure attempts (R12, R15) both regressed ~80us.
__global__ __launch_bounds__(256) void gather_gemm_kernel(
    const __half* __restrict__ hh_in, const float* __restrict__ b,
    const float* __restrict__ W, __half* __restrict__ hh_out)
{
    __shared__ float Ws[HID * HID];   // Ws[k*32 + col] = W[k][col]
    for (int i = threadIdx.x; i < HID * HID; i += 256) Ws[i] = W[i];
    __syncthreads();

    int node = blockIdx.x * 8 + (threadIdx.x >> 5);
    int lane = threadIdx.x & 31;
    int start = g_rowstart[node];
    int end   = g_rowstart[node + 1];

    float acc0 = 0.f, acc1 = 0.f;
    for (int base = start; base < end; base += 32) {
        int e = base + lane;
        int sidx = (e < end) ? g_csrc[e] : 0;
        int n = end - base;
        if (n >= 32) {
            #pragma unroll
            for (int j = 0; j < 32; j += 2) {
                int s0 = __shfl_sync(0xffffffffu, sidx, j);
                int s1 = __shfl_sync(0xffffffffu, sidx, j + 1);
                acc0 += __half2float(hh_in[(size_t)s0 * HID + lane]);
                acc1 += __half2float(hh_in[(size_t)s1 * HID + lane]);
            }
        } else {
            for (int j = 0; j < n; j++) {
                int s = __shfl_sync(0xffffffffu, sidx, j);
                acc0 += __half2float(hh_in[(size_t)s * HID + lane]);
            }
        }
    }
    float dv = g_dinv[node];
    float self = __half2float(hh_in[(size_t)node * HID + lane]);
    float v = fmaxf(dv * (acc0 + acc1 + self) + b[lane], 0.0f);

    float o = 0.f;
    #pragma unroll
    for (int k = 0; k < HID; k++) {
        float xv = __shfl_sync(0xffffffffu, v, k);
        o += xv * Ws[k * HID + lane];
    }
    hh_out[(size_t)node * HID + lane] = __float2half(o * dv);
}

// ---------------- fused layer-3 gather + MLP head (fp16 h) ----------------
__global__ __launch_bounds__(256) void gather_mlp_kernel(
    const __half* __restrict__ hh, const float* __restrict__ b3,
    const float* __restrict__ l1W, const float* __restrict__ l1b,
    const float* __restrict__ l2W, const float* __restrict__ l2b,
    float* __restrict__ out)
{
    int node = blockIdx.x * 8 + (threadIdx.x >> 5);
    int lane = threadIdx.x & 31;
    int start = g_rowstart[node];
    int end   = g_rowstart[node + 1];

    float acc0 = 0.f, acc1 = 0.f;
    for (int base = start; base < end; base += 32) {
        int e = base + lane;
        int sidx = (e < end) ? g_csrc[e] : 0;
        int n = end - base;
        if (n >= 32) {
            #pragma unroll
            for (int j = 0; j < 32; j += 2) {
                int s0 = __shfl_sync(0xffffffffu, sidx, j);
                int s1 = __shfl_sync(0xffffffffu, sidx, j + 1);
                acc0 += __half2float(hh[(size_t)s0 * HID + lane]);
                acc1 += __half2float(hh[(size_t)s1 * HID + lane]);
            }
        } else {
            for (int j = 0; j < n; j++) {
                int s = __shfl_sync(0xffffffffu, sidx, j);
                acc0 += __half2float(hh[(size_t)s * HID + lane]);
            }
        }
    }
    float dv = g_dinv[node];
    float self = __half2float(hh[(size_t)node * HID + lane]);
    float v = fmaxf(dv * (acc0 + acc1 + self) + b3[lane], 0.0f);  // x3

    // lin1: [32] -> [16], relu
    float a1 = 0.f;
    #pragma unroll
    for (int k = 0; k < 32; k++) {
        float xv = __shfl_sync(0xffffffffu, v, k);
        if (lane < 16) a1 += xv * l1W[k * 16 + lane];
    }
    float h1 = (lane < 16) ? fmaxf(a1 + l1b[lane], 0.0f) : 0.0f;

    // lin2: [16] -> [10]
    float a2 = 0.f;
    #pragma unroll
    for (int j = 0; j < 16; j++) {
        float hv = __shfl_sync(0xffffffffu, h1, j);
        if (lane < 10) a2 += hv * l2W[j * 10 + lane];
    }
    if (lane < 10) out[(size_t)node * 10 + lane] = a2 + l2b[lane];
}

// ---------------- host ----------------
extern "C" void kernel_launch(void* const* d_in, const int* in_sizes, int n_in,
                              void* d_out, int out_size)
{
    const float* x0  = (const float*)d_in[0];
    const int*   ei  = (const int*)d_in[1];   // edge_index int32
    // d_in[2] = batch (unused)
    const float* W1  = (const float*)d_in[3];
    const float* b1  = (const float*)d_in[4];
    const float* W2  = (const float*)d_in[5];
    const float* b2  = (const float*)d_in[6];
    const float* W3  = (const float*)d_in[7];
    const float* b3  = (const float*)d_in[8];
    const float* l1W = (const float*)d_in[9];
    const float* l1b = (const float*)d_in[10];
    const float* l2W = (const float*)d_in[11];
    const float* l2b = (const float*)d_in[12];
    float* out = (float*)d_out;

    const int* src = ei;
    const int* dst = ei + N_EDGES;

    __half *hbuf = nullptr, *abuf = nullptr;
    cudaGetSymbolAddress((void**)&hbuf, g_h);
    cudaGetSymbolAddress((void**)&abuf, g_agg);

    static cudaStream_t s_side = nullptr;
    static cudaEvent_t  s_fork = nullptr, s_join = nullptr;
    if (s_side == nullptr) {
        cudaStreamCreateWithFlags(&s_side, cudaStreamNonBlocking);
        cudaEventCreateWithFlags(&s_fork, cudaEventDisableTiming);
        cudaEventCreateWithFlags(&s_join, cudaEventDisableTiming);
        cudaFuncSetAttribute(gemm1_kernel,
                             cudaFuncAttributeMaxDynamicSharedMemorySize,
                             G1_SMEM_BYTES);
    }

    const int nodeBlocks = (N_NODES + 255) / 256;   // 391
    const int edgeBlocks = N_EDGES / 256;           // 12500
    const int warpBlocks = N_NODES / 8;             // 12500
    const int g1Blocks   = (N_NODES + G1_ROWS - 1) / G1_ROWS;  // 782

    // ---- degree prefix ----
    zero_degi_kernel<<<nodeBlocks, 256>>>();
    degi_kernel<<<edgeBlocks, 256>>>(dst);

    // ---- fork: gemm1 needs only g_degi (dinv computed in its epilogue) ----
    cudaEventRecord(s_fork, 0);
    cudaStreamWaitEvent(s_side, s_fork, 0);
    gemm1_kernel<<<g1Blocks, 256, G1_SMEM_BYTES, s_side>>>(x0, W1, hbuf);  // hh1

    // ---- CSR build tail (overlaps gemm1) ----
    scan_block_kernel<<<SCAN_NBLK, SCAN_BLK>>>();   // also computes g_dinv
    scan_tops_kernel<<<1, 256>>>();
    scan_add_kernel<<<nodeBlocks, 256>>>();
    fill_kernel<<<edgeBlocks, 256>>>(src, dst);

    // ---- join ----
    cudaEventRecord(s_join, s_side);
    cudaStreamWaitEvent(0, s_join, 0);

    // ---- gather1 + gemm2 fused ----
    gather_gemm_kernel<<<warpBlocks, 256>>>(hbuf, b1, W2, abuf);    // hh2

    // ---- gather2 + gemm3 fused ----
    gather_gemm_kernel<<<warpBlocks, 256>>>(abuf, b2, W3, hbuf);    // hh3

    // ---- gather3 + MLP head fused ----
    gather_mlp_kernel<<<warpBlocks, 256>>>(hbuf, b3, l1W, l1b, l2W, l2b, out);
}